// round 2
// baseline (speedup 1.0000x reference)
#include <cuda_runtime.h>

#define NEGV (-9e15f)

// 8 precomputed scalar contractions:
// [0]=W·a1  [1]=W·a2  [2]=WS·aS1  [3]=WS·aS2
// [4]=A0=WQ0·WK0/4 [5]=B0=WQ1·WK0/4 [6]=A1=WQ0·WK1/4 [7]=B1=WQ1·WK1/4
__device__ float g_c[8];

__global__ void prep_kernel(const float* __restrict__ W,  const float* __restrict__ a,
                            const float* __restrict__ WS, const float* __restrict__ aS,
                            const float* __restrict__ WQ, const float* __restrict__ WK) {
    int l = threadIdx.x;                       // 32 threads
    float v[8];
    v[0] = W[l]*a[l]       + W[l+32]*a[l+32];
    v[1] = W[l]*a[64+l]    + W[l+32]*a[96+l];
    v[2] = WS[l]*aS[l]     + WS[l+32]*aS[l+32];
    v[3] = WS[l]*aS[64+l]  + WS[l+32]*aS[96+l];
    bool lo = (l < 16);
    v[4] = lo ? WQ[l]   *WK[l]    : 0.f;       // WQ[0,:]·WK[0,:]
    v[5] = lo ? WQ[16+l]*WK[l]    : 0.f;       // WQ[1,:]·WK[0,:]
    v[6] = lo ? WQ[l]   *WK[16+l] : 0.f;       // WQ[0,:]·WK[1,:]
    v[7] = lo ? WQ[16+l]*WK[16+l] : 0.f;       // WQ[1,:]·WK[1,:]
    #pragma unroll
    for (int k = 0; k < 8; k++)
        #pragma unroll
        for (int o = 16; o; o >>= 1) v[k] += __shfl_xor_sync(0xffffffffu, v[k], o);
    if (l == 0) {
        g_c[0] = v[0]; g_c[1] = v[1]; g_c[2] = v[2]; g_c[3] = v[3];
        g_c[4] = v[4]*0.25f; g_c[5] = v[5]*0.25f;   // /sqrt(D), D=16
        g_c[6] = v[6]*0.25f; g_c[7] = v[7]*0.25f;
    }
}

constexpr int N  = 512;
constexpr int F  = 64;
constexpr int BS = 8;
constexpr int THREADS = 256;

__global__ __launch_bounds__(THREADS)
void gat_kernel(const float* __restrict__ x,    // input  [8,512,1]
                const int*   __restrict__ adj,  // [512,512]
                const float* __restrict__ ext,  // [8,512,8]
                const float* __restrict__ side, // [8,512,1]
                const float* __restrict__ W,    // [1,64]
                const float* __restrict__ WV,   // [1,64]
                float* __restrict__ out)        // [2, 8,512,64]
{
    __shared__ float s_logit[N];
    __shared__ float s_x[N];
    __shared__ float s_red[8];
    __shared__ float s_sum[3][8];
    __shared__ float s_bcast[3];

    const int row = blockIdx.x;          // b*512 + i
    const int b   = row >> 9;
    const int i   = row & 511;
    const int tid = threadIdx.x;

    const float c1 = g_c[0], c2 = g_c[1], cs1 = g_c[2], cs2 = g_c[3];
    const float A0 = g_c[4], B0 = g_c[5], A1  = g_c[6], B1  = g_c[7];

    const float xi = x[row];
    const float si = side[row];
    float ei[8];
    {
        const float4* e4 = (const float4*)(ext + (size_t)row * 8);
        float4 ea = e4[0], eb = e4[1];
        ei[0]=ea.x; ei[1]=ea.y; ei[2]=ea.z; ei[3]=ea.w;
        ei[4]=eb.x; ei[5]=eb.y; ei[6]=eb.z; ei[7]=eb.w;
    }
    const float t1 = xi * c1;
    const float t2 = si * cs1;

    // ---- Pass A: attention logits + row max ----
    float lmax = NEGV;
    #pragma unroll
    for (int j = tid; j < N; j += THREADS) {
        float xj = x[(b << 9) + j];
        float sj = side[(b << 9) + j];
        int  aij = adj[(i << 9) + j];
        float e  = t1 + xj * c2;   e  = (e  > 0.f) ? e  : 0.2f * e;   // leakyrelu
        float es = t2 + sj * cs2;  es = (es > 0.f) ? es : 0.2f * es;
        float s  = e + es;
        float logit = (aij > 0 && s > 0.f) ? s : NEGV;
        s_logit[j] = logit;
        s_x[j]     = xj;
        lmax = fmaxf(lmax, logit);
    }
    #pragma unroll
    for (int o = 16; o; o >>= 1) lmax = fmaxf(lmax, __shfl_xor_sync(0xffffffffu, lmax, o));
    if ((tid & 31) == 0) s_red[tid >> 5] = lmax;
    __syncthreads();
    if (tid == 0) {
        float m = s_red[0];
        #pragma unroll
        for (int k = 1; k < 8; k++) m = fmaxf(m, s_red[k]);
        s_bcast[0] = m;
    }
    __syncthreads();
    const float m = s_bcast[0];

    // ---- Pass B: exp, denominator, y-numerator, z-numerator ----
    float den = 0.f, ynum = 0.f, znum = 0.f;
    #pragma unroll
    for (int j = tid; j < N; j += THREADS) {
        float p  = __expf(s_logit[j] - m);
        float xj = s_x[j];
        den  += p;
        ynum += p * xj;
        if (p != 0.f) {
            float qk0 = xi * A0 + xj * B0;
            float qk1 = xi * A1 + xj * B1;
            const float4* f4 = (const float4*)(ext + (size_t)(((b << 9) + j)) * 8);
            float4 fa = f4[0], fb = f4[1];
            float ej[8] = {fa.x, fa.y, fa.z, fa.w, fb.x, fb.y, fb.z, fb.w};
            float d[8];
            float m8 = NEGV;
            #pragma unroll
            for (int f = 0; f < 8; f++) {
                float df = ei[f] * qk0 + ej[f] * qk1;
                df = (df > 0.f) ? df : NEGV;
                d[f] = df;
                m8 = fmaxf(m8, df);
            }
            float s8 = 0.f, wn = 0.f;
            #pragma unroll
            for (int f = 0; f < 8; f++) {
                float pf = __expf(d[f] - m8);
                s8 += pf;
                wn += pf * ei[f];
            }
            znum += p * (wn / s8);
        }
    }
    #pragma unroll
    for (int o = 16; o; o >>= 1) {
        den  += __shfl_xor_sync(0xffffffffu, den,  o);
        ynum += __shfl_xor_sync(0xffffffffu, ynum, o);
        znum += __shfl_xor_sync(0xffffffffu, znum, o);
    }
    if ((tid & 31) == 0) {
        int w = tid >> 5;
        s_sum[0][w] = den; s_sum[1][w] = ynum; s_sum[2][w] = znum;
    }
    __syncthreads();
    if (tid == 0) {
        float D = 0.f, Y = 0.f, Z = 0.f;
        #pragma unroll
        for (int k = 0; k < 8; k++) { D += s_sum[0][k]; Y += s_sum[1][k]; Z += s_sum[2][k]; }
        s_bcast[1] = Y / D;
        s_bcast[2] = Z / D;
    }
    __syncthreads();
    const float y = s_bcast[1];
    const float z = s_bcast[2];

    // ---- outputs: elu(y*W[f]) and elu(z*WV[f]) ----
    if (tid < F) {
        float v1 = y * W[tid];
        v1 = (v1 > 0.f) ? v1 : expm1f(v1);
        out[(size_t)row * F + tid] = v1;
        float v2 = z * WV[tid];
        v2 = (v2 > 0.f) ? v2 : expm1f(v2);
        out[(size_t)BS * N * F + (size_t)row * F + tid] = v2;
    }
}

extern "C" void kernel_launch(void* const* d_in, const int* in_sizes, int n_in,
                              void* d_out, int out_size) {
    const float* input = (const float*)d_in[0];
    const int*   adj   = (const int*)  d_in[1];
    const float* ext   = (const float*)d_in[2];
    const float* side  = (const float*)d_in[3];
    const float* W     = (const float*)d_in[4];
    const float* a     = (const float*)d_in[5];
    const float* WS    = (const float*)d_in[6];
    const float* aS    = (const float*)d_in[7];
    const float* WQ    = (const float*)d_in[8];
    const float* WK    = (const float*)d_in[9];
    const float* WV    = (const float*)d_in[10];
    float* out = (float*)d_out;

    prep_kernel<<<1, 32>>>(W, a, WS, aS, WQ, WK);
    gat_kernel<<<BS * N, THREADS>>>(input, adj, ext, side, W, WV, out);
}

// round 3
// speedup vs baseline: 1.0078x; 1.0078x over previous
#include <cuda_runtime.h>

#define NEGV (-9e15f)

// 8 precomputed scalar contractions:
// [0]=W·a1  [1]=W·a2  [2]=WS·aS1  [3]=WS·aS2
// [4]=A0=WQ0·WK0/4 [5]=B0=WQ1·WK0/4 [6]=A1=WQ0·WK1/4 [7]=B1=WQ1·WK1/4
__device__ float g_c[8];

__global__ void prep_kernel(const float* __restrict__ W,  const float* __restrict__ a,
                            const float* __restrict__ WS, const float* __restrict__ aS,
                            const float* __restrict__ WQ, const float* __restrict__ WK) {
    int l = threadIdx.x;                       // 32 threads
    float v[8];
    v[0] = W[l]*a[l]       + W[l+32]*a[l+32];
    v[1] = W[l]*a[64+l]    + W[l+32]*a[96+l];
    v[2] = WS[l]*aS[l]     + WS[l+32]*aS[l+32];
    v[3] = WS[l]*aS[64+l]  + WS[l+32]*aS[96+l];
    bool lo = (l < 16);
    v[4] = lo ? WQ[l]   *WK[l]    : 0.f;       // WQ[0,:]·WK[0,:]
    v[5] = lo ? WQ[16+l]*WK[l]    : 0.f;       // WQ[1,:]·WK[0,:]
    v[6] = lo ? WQ[l]   *WK[16+l] : 0.f;       // WQ[0,:]·WK[1,:]
    v[7] = lo ? WQ[16+l]*WK[16+l] : 0.f;       // WQ[1,:]·WK[1,:]
    #pragma unroll
    for (int k = 0; k < 8; k++)
        #pragma unroll
        for (int o = 16; o; o >>= 1) v[k] += __shfl_xor_sync(0xffffffffu, v[k], o);
    if (l == 0) {
        g_c[0] = v[0]; g_c[1] = v[1]; g_c[2] = v[2]; g_c[3] = v[3];
        g_c[4] = v[4]*0.25f; g_c[5] = v[5]*0.25f;   // /sqrt(D), D=16
        g_c[6] = v[6]*0.25f; g_c[7] = v[7]*0.25f;
    }
}

constexpr int N  = 512;
constexpr int F  = 64;
constexpr int BS = 8;
constexpr int THREADS = 256;

__global__ __launch_bounds__(THREADS)
void gat_kernel(const float* __restrict__ x,    // input  [8,512,1]
                const int*   __restrict__ adj,  // [512,512]
                const float* __restrict__ ext,  // [8,512,8]
                const float* __restrict__ side, // [8,512,1]
                const float* __restrict__ W,    // [1,64]
                const float* __restrict__ WV,   // [1,64]
                float* __restrict__ out)        // [2, 8,512,64]
{
    __shared__ float s_logit[N];
    __shared__ float s_x[N];
    __shared__ float s_red[8];
    __shared__ float s_sum[3][8];
    __shared__ float s_bcast[3];

    const int row = blockIdx.x;          // b*512 + i
    const int b   = row >> 9;
    const int i   = row & 511;
    const int tid = threadIdx.x;

    const float c1 = g_c[0], c2 = g_c[1], cs1 = g_c[2], cs2 = g_c[3];
    const float A0 = g_c[4], B0 = g_c[5], A1  = g_c[6], B1  = g_c[7];

    const float xi = x[row];
    const float si = side[row];
    float ei[8];
    {
        const float4* e4 = (const float4*)(ext + (size_t)row * 8);
        float4 ea = e4[0], eb = e4[1];
        ei[0]=ea.x; ei[1]=ea.y; ei[2]=ea.z; ei[3]=ea.w;
        ei[4]=eb.x; ei[5]=eb.y; ei[6]=eb.z; ei[7]=eb.w;
    }
    const float t1 = xi * c1;
    const float t2 = si * cs1;

    // ---- Pass A: attention logits + row max ----
    float lmax = NEGV;
    #pragma unroll
    for (int j = tid; j < N; j += THREADS) {
        float xj = x[(b << 9) + j];
        float sj = side[(b << 9) + j];
        int  aij = adj[(i << 9) + j];
        float e  = t1 + xj * c2;   e  = (e  > 0.f) ? e  : 0.2f * e;   // leakyrelu
        float es = t2 + sj * cs2;  es = (es > 0.f) ? es : 0.2f * es;
        float s  = e + es;
        float logit = (aij > 0 && s > 0.f) ? s : NEGV;
        s_logit[j] = logit;
        s_x[j]     = xj;
        lmax = fmaxf(lmax, logit);
    }
    #pragma unroll
    for (int o = 16; o; o >>= 1) lmax = fmaxf(lmax, __shfl_xor_sync(0xffffffffu, lmax, o));
    if ((tid & 31) == 0) s_red[tid >> 5] = lmax;
    __syncthreads();
    if (tid == 0) {
        float m = s_red[0];
        #pragma unroll
        for (int k = 1; k < 8; k++) m = fmaxf(m, s_red[k]);
        s_bcast[0] = m;
    }
    __syncthreads();
    const float m = s_bcast[0];

    // ---- Pass B: exp, denominator, y-numerator, z-numerator ----
    float den = 0.f, ynum = 0.f, znum = 0.f;
    #pragma unroll
    for (int j = tid; j < N; j += THREADS) {
        float p  = __expf(s_logit[j] - m);
        float xj = s_x[j];
        den  += p;
        ynum += p * xj;
        if (p != 0.f) {
            float qk0 = xi * A0 + xj * B0;
            float qk1 = xi * A1 + xj * B1;
            const float4* f4 = (const float4*)(ext + (size_t)(((b << 9) + j)) * 8);
            float4 fa = f4[0], fb = f4[1];
            float ej[8] = {fa.x, fa.y, fa.z, fa.w, fb.x, fb.y, fb.z, fb.w};
            float d[8];
            float m8 = NEGV;
            #pragma unroll
            for (int f = 0; f < 8; f++) {
                float df = ei[f] * qk0 + ej[f] * qk1;
                df = (df > 0.f) ? df : NEGV;
                d[f] = df;
                m8 = fmaxf(m8, df);
            }
            float s8 = 0.f, wn = 0.f;
            #pragma unroll
            for (int f = 0; f < 8; f++) {
                float pf = __expf(d[f] - m8);
                s8 += pf;
                wn += pf * ei[f];
            }
            znum += p * (wn / s8);
        }
    }
    #pragma unroll
    for (int o = 16; o; o >>= 1) {
        den  += __shfl_xor_sync(0xffffffffu, den,  o);
        ynum += __shfl_xor_sync(0xffffffffu, ynum, o);
        znum += __shfl_xor_sync(0xffffffffu, znum, o);
    }
    if ((tid & 31) == 0) {
        int w = tid >> 5;
        s_sum[0][w] = den; s_sum[1][w] = ynum; s_sum[2][w] = znum;
    }
    __syncthreads();
    if (tid == 0) {
        float D = 0.f, Y = 0.f, Z = 0.f;
        #pragma unroll
        for (int k = 0; k < 8; k++) { D += s_sum[0][k]; Y += s_sum[1][k]; Z += s_sum[2][k]; }
        s_bcast[1] = Y / D;
        s_bcast[2] = Z / D;
    }
    __syncthreads();
    const float y = s_bcast[1];
    const float z = s_bcast[2];

    // ---- outputs: elu(y*W[f]) and elu(z*WV[f]) ----
    if (tid < F) {
        float v1 = y * W[tid];
        v1 = (v1 > 0.f) ? v1 : expm1f(v1);
        out[(size_t)row * F + tid] = v1;
        float v2 = z * WV[tid];
        v2 = (v2 > 0.f) ? v2 : expm1f(v2);
        out[(size_t)BS * N * F + (size_t)row * F + tid] = v2;
    }
}

extern "C" void kernel_launch(void* const* d_in, const int* in_sizes, int n_in,
                              void* d_out, int out_size) {
    const float* input = (const float*)d_in[0];
    const int*   adj   = (const int*)  d_in[1];
    const float* ext   = (const float*)d_in[2];
    const float* side  = (const float*)d_in[3];
    const float* W     = (const float*)d_in[4];
    const float* a     = (const float*)d_in[5];
    const float* WS    = (const float*)d_in[6];
    const float* aS    = (const float*)d_in[7];
    const float* WQ    = (const float*)d_in[8];
    const float* WK    = (const float*)d_in[9];
    const float* WV    = (const float*)d_in[10];
    float* out = (float*)d_out;

    prep_kernel<<<1, 32>>>(W, a, WS, aS, WQ, WK);
    gat_kernel<<<BS * N, THREADS>>>(input, adj, ext, side, W, WV, out);
}

// round 4
// speedup vs baseline: 1.5147x; 1.5029x over previous
#include <cuda_runtime.h>

#define NEGV (-9e15f)

constexpr int N  = 512;
constexpr int F  = 64;
constexpr int BS = 8;
constexpr int WARPS = 8;
constexpr int THREADS = WARPS * 32;
constexpr int OUT_OFF = BS * N * F;   // 262144

__global__ __launch_bounds__(THREADS)
void gat_kernel(const float* __restrict__ x,    // [8,512,1]
                const int*   __restrict__ adj,  // [512,512]
                const float* __restrict__ ext,  // [8,512,8]
                const float* __restrict__ side, // [8,512,1]
                const float* __restrict__ W,    // [1,64]
                const float* __restrict__ a,    // [128,1]
                const float* __restrict__ WS,   // [1,64]
                const float* __restrict__ aS,   // [128,1]
                const float* __restrict__ WQ,   // [2,16]
                const float* __restrict__ WK,   // [2,16]
                const float* __restrict__ WV,   // [1,64]
                float* __restrict__ out)        // [2,8,512,64]
{
    __shared__ float          s_log[WARPS][N];
    __shared__ unsigned short s_j  [WARPS][N];

    const int lane = threadIdx.x & 31;
    const int w    = threadIdx.x >> 5;
    const int row  = blockIdx.x * WARPS + w;   // b*512 + i
    const int b    = row >> 9;
    const int i    = row & 511;

    // ---- fused prep: 8 scalar contractions per warp (amortized, L1-hot) ----
    const float Wl  = W[lane],  Wh  = W[lane + 32];
    const float WVl = WV[lane], WVh = WV[lane + 32];
    {
        // nothing: just keep loads hoisted
    }
    float r0, r1, r2, r3, r4, r5, r6, r7;
    {
        float WSl = WS[lane], WSh = WS[lane + 32];
        int l16 = lane & 15;
        float wq0 = WQ[l16], wq1 = WQ[16 + l16];
        float wk0 = WK[l16], wk1 = WK[16 + l16];
        r0 = Wl  * a[lane]       + Wh  * a[32 + lane];
        r1 = Wl  * a[64 + lane]  + Wh  * a[96 + lane];
        r2 = WSl * aS[lane]      + WSh * aS[32 + lane];
        r3 = WSl * aS[64 + lane] + WSh * aS[96 + lane];
        r4 = wq0 * wk0;  r5 = wq1 * wk0;   // half-lanes duplicated -> x0.5 below
        r6 = wq0 * wk1;  r7 = wq1 * wk1;
        #pragma unroll
        for (int o = 16; o; o >>= 1) {
            r0 += __shfl_xor_sync(0xffffffffu, r0, o);
            r1 += __shfl_xor_sync(0xffffffffu, r1, o);
            r2 += __shfl_xor_sync(0xffffffffu, r2, o);
            r3 += __shfl_xor_sync(0xffffffffu, r3, o);
            r4 += __shfl_xor_sync(0xffffffffu, r4, o);
            r5 += __shfl_xor_sync(0xffffffffu, r5, o);
            r6 += __shfl_xor_sync(0xffffffffu, r6, o);
            r7 += __shfl_xor_sync(0xffffffffu, r7, o);
        }
    }
    const float c1 = r0, c2 = r1, cs1 = r2, cs2 = r3;
    // 0.5 (lane dedup) * 0.25 (1/sqrt(D), D=16) = 0.125
    const float A0 = r4 * 0.125f, B0 = r5 * 0.125f;
    const float A1 = r6 * 0.125f, B1 = r7 * 0.125f;

    const float xi = x[row];
    const float si = side[row];
    float ei[8];
    {
        const float4* e4 = (const float4*)(ext + (size_t)row * 8);
        float4 ea = e4[0], eb = e4[1];
        ei[0]=ea.x; ei[1]=ea.y; ei[2]=ea.z; ei[3]=ea.w;
        ei[4]=eb.x; ei[5]=eb.y; ei[6]=eb.z; ei[7]=eb.w;
    }
    const float mean_ei = (ei[0]+ei[1]+ei[2]+ei[3]+ei[4]+ei[5]+ei[6]+ei[7]) * 0.125f;
    const float t1 = xi * c1;
    const float t2 = si * cs1;

    const float* xb = x    + (b << 9);
    const float* sb = side + (b << 9);
    const int*   ar = adj  + (i << 9);

    // ---- Pass A: logits, row max, warp-ballot compaction of active j ----
    float lmax = NEGV;
    int   cnt  = 0;
    #pragma unroll
    for (int jj = 0; jj < N / 32; jj++) {
        int   j  = jj * 32 + lane;
        float xj = xb[j];
        float sj = sb[j];
        int  aij = ar[j];
        float e  = t1 + xj * c2;   e  = fmaxf(e,  0.2f * e);   // leakyrelu
        float es = t2 + sj * cs2;  es = fmaxf(es, 0.2f * es);
        float s  = e + es;
        bool act = (aij > 0) && (s > 0.f);
        unsigned mk = __ballot_sync(0xffffffffu, act);
        if (act) {
            int pos = cnt + __popc(mk & ((1u << lane) - 1u));
            s_j[w][pos]   = (unsigned short)j;
            s_log[w][pos] = s;
            lmax = fmaxf(lmax, s);
        }
        cnt += __popc(mk);
    }
    #pragma unroll
    for (int o = 16; o; o >>= 1)
        lmax = fmaxf(lmax, __shfl_xor_sync(0xffffffffu, lmax, o));

    // Degenerate row (no active j): reference softmax becomes uniform over all j
    // (m = NEGV, p = exp(NEGV - NEGV) = 1 for every j).
    if (cnt == 0) {
        #pragma unroll
        for (int jj = 0; jj < N / 32; jj++) {
            int j = jj * 32 + lane;
            s_j[w][j]   = (unsigned short)j;
            s_log[w][j] = NEGV;
        }
        cnt = N;
    }
    const float m = lmax;

    // ---- Pass B: only active j's, all lanes doing useful work ----
    float den = 0.f, ynum = 0.f, znum = 0.f;
    for (int t = lane; t < cnt; t += 32) {
        int   j  = s_j[w][t];
        float p  = __expf(s_log[w][t] - m);
        float xj = xb[j];
        den  += p;
        ynum += p * xj;
        float qk0 = xi * A0 + xj * B0;
        float qk1 = xi * A1 + xj * B1;
        const float4* f4 = (const float4*)(ext + (((size_t)(b << 9) + j)) * 8);
        float4 fa = f4[0], fb = f4[1];
        float ej[8] = {fa.x, fa.y, fa.z, fa.w, fb.x, fb.y, fb.z, fb.w};
        float s8 = 0.f, wn = 0.f;
        #pragma unroll
        for (int f = 0; f < 8; f++) {
            float df = ei[f] * qk0 + ej[f] * qk1;
            // active df's are positive & bounded -> exp is fp32-safe w/o max-sub
            float pf = (df > 0.f) ? __expf(df) : 0.f;
            s8 += pf;
            wn += pf * ei[f];
        }
        // all-negative inner row -> reference softmax is uniform -> mean(ei)
        znum += p * ((s8 > 0.f) ? __fdividef(wn, s8) : mean_ei);
    }
    #pragma unroll
    for (int o = 16; o; o >>= 1) {
        den  += __shfl_xor_sync(0xffffffffu, den,  o);
        ynum += __shfl_xor_sync(0xffffffffu, ynum, o);
        znum += __shfl_xor_sync(0xffffffffu, znum, o);
    }
    const float y = ynum / den;
    const float z = znum / den;

    // ---- outputs: elu(y*W[f]), elu(z*WV[f]) ----
    size_t base = (size_t)row * F + lane;
    float v;
    v = y * Wl;   out[base]                 = (v > 0.f) ? v : expm1f(v);
    v = y * Wh;   out[base + 32]            = (v > 0.f) ? v : expm1f(v);
    v = z * WVl;  out[OUT_OFF + base]       = (v > 0.f) ? v : expm1f(v);
    v = z * WVh;  out[OUT_OFF + base + 32]  = (v > 0.f) ? v : expm1f(v);
}

extern "C" void kernel_launch(void* const* d_in, const int* in_sizes, int n_in,
                              void* d_out, int out_size) {
    const float* input = (const float*)d_in[0];
    const int*   adj   = (const int*)  d_in[1];
    const float* ext   = (const float*)d_in[2];
    const float* side  = (const float*)d_in[3];
    const float* W     = (const float*)d_in[4];
    const float* a     = (const float*)d_in[5];
    const float* WS    = (const float*)d_in[6];
    const float* aS    = (const float*)d_in[7];
    const float* WQ    = (const float*)d_in[8];
    const float* WK    = (const float*)d_in[9];
    const float* WV    = (const float*)d_in[10];
    float* out = (float*)d_out;

    gat_kernel<<<(BS * N) / WARPS, THREADS>>>(input, adj, ext, side,
                                              W, a, WS, aS, WQ, WK, WV, out);
}